// round 10
// baseline (speedup 1.0000x reference)
#include <cuda_runtime.h>
#include <cuda_bf16.h>
#include <math.h>
#include <stdint.h>

// Problem constants
#define BATCH 4096
#define DIM   512
#define NTOT  8192
#define TILE  128
#define KBYTES  128              // int8 elems (=bytes) per K-chunk
#define NCHUNKS (DIM / KBYTES)   // 4
#define NTILES  (NTOT / TILE)    // 64
#define NCTAS   (NTILES * (NTILES + 1) / 2)  // 2080 upper-tri tiles

// SMEM: double-buffered A and B tiles, each 128 rows x 128 int8 = 16 KB
#define TILE_BYTES 16384
#define SM_A(buf) ((buf) * TILE_BYTES)
#define SM_B(buf) (2 * TILE_BYTES + (buf) * TILE_BYTES)
#define SM_TOTAL  (4 * TILE_BYTES)   // 64 KB -> 2 CTAs/SM (reg-bound anyway)

// Scratch (no cudaMalloc allowed)
__device__ uint32_t g_zq[NTOT * (DIM / 4)];  // int8-quantized Z, packed (4 MB)
__device__ float g_scale[NTOT];              // per-row dequant scale = max|z|/127
__device__ float g_denom[NTOT];
__device__ float g_pos[NTOT];

// ---------------------------------------------------------------------------
__device__ __forceinline__ uint32_t smem_u32(const void* p) {
    uint32_t a;
    asm("{ .reg .u64 t; cvta.to.shared.u64 t, %1; cvt.u32.u64 %0, t; }" : "=r"(a) : "l"(p));
    return a;
}

__device__ __forceinline__ void cp_async16(uint32_t saddr, const void* gptr) {
    asm volatile("cp.async.cg.shared.global [%0], [%1], 16;" :: "r"(saddr), "l"(gptr));
}
__device__ __forceinline__ void cp_commit() {
    asm volatile("cp.async.commit_group;" ::: "memory");
}
template <int N>
__device__ __forceinline__ void cp_wait() {
    asm volatile("cp.async.wait_group %0;" :: "n"(N) : "memory");
}

__device__ __forceinline__ void ldsm_x4(uint32_t* r, uint32_t addr) {
    asm volatile("ldmatrix.sync.aligned.m8n8.x4.shared.b16 {%0,%1,%2,%3}, [%4];"
                 : "=r"(r[0]), "=r"(r[1]), "=r"(r[2]), "=r"(r[3]) : "r"(addr));
}

// int8 IMMA: m16n8k32, s32 accumulate. Fragment byte layout identical to the
// bf16 m16n8k16 fragments, so ldmatrix.b16 addressing carries over unchanged.
__device__ __forceinline__ void mma16832(int* c, const uint32_t* a, const uint32_t* b) {
    asm volatile(
        "mma.sync.aligned.m16n8k32.row.col.s32.s8.s8.s32 "
        "{%0,%1,%2,%3}, {%4,%5,%6,%7}, {%8,%9}, {%0,%1,%2,%3};"
        : "+r"(c[0]), "+r"(c[1]), "+r"(c[2]), "+r"(c[3])
        : "r"(a[0]), "r"(a[1]), "r"(a[2]), "r"(a[3]), "r"(b[0]), "r"(b[1]));
}

// Fast exp(2*s) on the FMA pipe (avoid MUFU.EX2 throughput wall).
__device__ __forceinline__ float fast_exp2s(float s) {
    float t = 2.8853900817779268f * s;      // 2 * log2(e)
    float fn = rintf(t);
    float f = t - fn;
    float p = fmaf(0.0013333558f, f, 0.0096181291f);
    p = fmaf(p, f, 0.0555041087f);
    p = fmaf(p, f, 0.2402265070f);
    p = fmaf(p, f, 0.6931471806f);
    p = fmaf(p, f, 1.0f);
    int n = (int)fn;
    float scale = __int_as_float((n + 127) << 23);
    return p * scale;
}

// ---------------------------------------------------------------------------
// Kernel 1: L2-normalize rows, per-row max-abs scale, quantize to int8.
// One WARP per row; coalesced loads and packed uint32 stores.
// ---------------------------------------------------------------------------
__global__ __launch_bounds__(256) void norm_kernel(const float* __restrict__ xi,
                                                   const float* __restrict__ xj) {
    const int row = (blockIdx.x * 256 + threadIdx.x) >> 5;
    const int lane = threadIdx.x & 31;
    const float* src = (row < BATCH) ? (xi + (size_t)row * DIM)
                                     : (xj + (size_t)(row - BATCH) * DIM);
    float4 v[4];
    #pragma unroll
    for (int i = 0; i < 4; i++) v[i] = ((const float4*)src)[lane + 32 * i];

    float ss = 0.0f;
    #pragma unroll
    for (int i = 0; i < 4; i++)
        ss += v[i].x * v[i].x + v[i].y * v[i].y + v[i].z * v[i].z + v[i].w * v[i].w;
    #pragma unroll
    for (int o = 16; o > 0; o >>= 1) ss += __shfl_xor_sync(0xFFFFFFFFu, ss, o);

    const float inv = 1.0f / fmaxf(sqrtf(ss), 1e-12f);

    float z[16];
    #pragma unroll
    for (int i = 0; i < 4; i++) {
        z[4 * i + 0] = v[i].x * inv;
        z[4 * i + 1] = v[i].y * inv;
        z[4 * i + 2] = v[i].z * inv;
        z[4 * i + 3] = v[i].w * inv;
    }

    float m = 0.0f;
    #pragma unroll
    for (int j = 0; j < 16; j++) m = fmaxf(m, fabsf(z[j]));
    #pragma unroll
    for (int o = 16; o > 0; o >>= 1) m = fmaxf(m, __shfl_xor_sync(0xFFFFFFFFu, m, o));
    m = fmaxf(m, 1e-20f);

    const float qs = 127.0f / m;
    #pragma unroll
    for (int i = 0; i < 4; i++) {
        int a0 = __float2int_rn(z[4 * i + 0] * qs);
        int a1 = __float2int_rn(z[4 * i + 1] * qs);
        int a2 = __float2int_rn(z[4 * i + 2] * qs);
        int a3 = __float2int_rn(z[4 * i + 3] * qs);
        uint32_t u = (uint32_t)(a0 & 0xFF) | ((uint32_t)(a1 & 0xFF) << 8)
                   | ((uint32_t)(a2 & 0xFF) << 16) | ((uint32_t)(a3 & 0xFF) << 24);
        g_zq[(size_t)row * (DIM / 4) + lane + 32 * i] = u;
    }

    if (lane == 0) {
        g_scale[row] = m * (1.0f / 127.0f);
        g_denom[row] = 0.0f;
        g_pos[row] = 0.0f;
    }
}

// ---------------------------------------------------------------------------
// Kernel 2: symmetric-aware fused sim tiles (upper-tri only) — R5 schedule
// shape, int8 IMMA mainloop (half the instructions and half the smem traffic
// of bf16), scale-dequant + exp/rowsum/colsum epilogue.
// ---------------------------------------------------------------------------
__global__ __launch_bounds__(256, 2) void sim_kernel() {
    extern __shared__ char smem[];
    const uint32_t sbase = smem_u32(smem);
    const int tid = threadIdx.x;
    const int wid = tid >> 5;
    const int lane = tid & 31;

    // triangular decode: off(i) = i*64 - i*(i-1)/2
    const int t = blockIdx.x;
    int by = (int)(64.5f - sqrtf(64.5f * 64.5f - 2.0f * (float)t));
    while ((by + 1) * NTILES - ((by + 1) * by) / 2 <= t) by++;
    while (by * NTILES - (by * (by - 1)) / 2 > t) by--;
    const int bx = by + (t - (by * NTILES - (by * (by - 1)) / 2));

    const int rowBase = by * TILE;
    const int colBase = bx * TILE;
    const bool diag = (by == bx);

    const int warp_m = wid & 3;     // 0..3 -> 32-row strip
    const int warp_n = wid >> 2;    // 0..1 -> 64-col strip

    const int8_t* __restrict__ zq = (const int8_t*)g_zq;

    // --- cp.async load mapping: 1024 16B units per tile, 4 per thread ---
    // rows are 128 bytes (128 int8) -> identical addressing to the bf16 build
    uint32_t ld_soff[4];
    const int8_t* ld_ga[4];
    const int8_t* ld_gb[4];
    #pragma unroll
    for (int it = 0; it < 4; it++) {
        int idx = tid + it * 256;
        int r = idx >> 3;
        int c16 = idx & 7;
        ld_soff[it] = (uint32_t)(r * 128 + ((c16 * 16) ^ ((r & 7) << 4)));
        ld_ga[it] = zq + (size_t)(rowBase + r) * DIM + c16 * 16;
        ld_gb[it] = zq + (size_t)(colBase + r) * DIM + c16 * 16;
    }

    // --- ldmatrix address components (byte-identical to bf16 k16 case) ---
    uint32_t aRow[2], aMask[2];
    #pragma unroll
    for (int mt = 0; mt < 2; mt++) {
        int r = warp_m * 32 + mt * 16 + (lane & 15);
        aRow[mt] = (uint32_t)(r * 128);
        aMask[mt] = (uint32_t)((r & 7) << 4);
    }
    const uint32_t aColK = (uint32_t)((lane >> 4) * 16);

    uint32_t bRow[4], bMask[4];
    const int q = lane >> 3;
    #pragma unroll
    for (int p = 0; p < 4; p++) {
        int r = warp_n * 64 + (2 * p + (q >> 1)) * 8 + (lane & 7);
        bRow[p] = (uint32_t)(r * 128);
        bMask[p] = (uint32_t)((r & 7) << 4);
    }
    const uint32_t bColK = (uint32_t)((q & 1) * 16);

    int acc[2][8][4];
    #pragma unroll
    for (int mt = 0; mt < 2; mt++)
        #pragma unroll
        for (int nt = 0; nt < 8; nt++)
            #pragma unroll
            for (int k = 0; k < 4; k++) acc[mt][nt][k] = 0;

    // --- prologue: chunk 0 -> buffer 0 ---
    #pragma unroll
    for (int it = 0; it < 4; it++) {
        cp_async16(sbase + SM_A(0) + ld_soff[it], ld_ga[it]);
        cp_async16(sbase + SM_B(0) + ld_soff[it], ld_gb[it]);
    }
    cp_commit();

    for (int kk = 0; kk < NCHUNKS; kk++) {
        const int buf = kk & 1;
        if (kk + 1 < NCHUNKS) {
            const int nb = (kk + 1) & 1;
            const int koff = (kk + 1) * KBYTES;
            #pragma unroll
            for (int it = 0; it < 4; it++) {
                cp_async16(sbase + SM_A(nb) + ld_soff[it], ld_ga[it] + koff);
                cp_async16(sbase + SM_B(nb) + ld_soff[it], ld_gb[it] + koff);
            }
            cp_commit();
            cp_wait<1>();
        } else {
            cp_wait<0>();
        }
        __syncthreads();

        const uint32_t abase = sbase + SM_A(buf);
        const uint32_t bbase = sbase + SM_B(buf);

        #pragma unroll
        for (int kt = 0; kt < 4; kt++) {       // each kt covers K=32 int8
            const uint32_t kb = (uint32_t)(kt * 32);
            uint32_t a[2][4];
            #pragma unroll
            for (int mt = 0; mt < 2; mt++)
                ldsm_x4(a[mt], abase + aRow[mt] + ((kb + aColK) ^ aMask[mt]));

            uint32_t b[8][2];
            #pragma unroll
            for (int p = 0; p < 4; p++) {
                uint32_t r4[4];
                ldsm_x4(r4, bbase + bRow[p] + ((kb + bColK) ^ bMask[p]));
                b[2 * p][0] = r4[0]; b[2 * p][1] = r4[1];
                b[2 * p + 1][0] = r4[2]; b[2 * p + 1][1] = r4[3];
            }

            #pragma unroll
            for (int mt = 0; mt < 2; mt++)
                #pragma unroll
                for (int nt = 0; nt < 8; nt++)
                    mma16832(acc[mt][nt], a[mt], b[nt]);
        }
        __syncthreads();   // protect buffers before next iteration's cp.async
    }

    // --- stage dequant scales into (now free) smem ---
    float* sRow = (float*)smem;          // [128]
    float* sCol = (float*)(smem + 512);  // [128]
    if (tid < 128) sRow[tid] = g_scale[rowBase + tid];
    else           sCol[tid - 128] = g_scale[colBase + (tid - 128)];
    __syncthreads();

    // --- fused epilogue (dequant + exp + row/col sums) ---
    // fragment map: c0,c1 -> row g=lane>>2, cols cb0, cb0+1 ; c2,c3 -> row g+8
    const int g = lane >> 2;
    const int cl0 = warp_n * 64 + (lane & 3) * 2;   // local col of c0
    const int cb0 = colBase + cl0;

    if (diag) {
        #pragma unroll
        for (int mt = 0; mt < 2; mt++) {
            const int rl = warp_m * 32 + mt * 16 + g;
            const int r_lo = rowBase + rl;
            const int r_hi = r_lo + 8;
            const float sr_lo = sRow[rl];
            const float sr_hi = sRow[rl + 8];
            float sum_lo = 0.0f, sum_hi = 0.0f;
            #pragma unroll
            for (int nt = 0; nt < 8; nt++) {
                const int c0 = cb0 + nt * 8;
                const float sc0 = sCol[cl0 + nt * 8];
                const float sc1 = sCol[cl0 + nt * 8 + 1];
                const float s00 = (float)acc[mt][nt][0] * sr_lo * sc0;
                const float s01 = (float)acc[mt][nt][1] * sr_lo * sc1;
                const float s10 = (float)acc[mt][nt][2] * sr_hi * sc0;
                const float s11 = (float)acc[mt][nt][3] * sr_hi * sc1;
                if (c0 != r_lo)     sum_lo += fast_exp2s(s00);
                if (c0 + 1 != r_lo) sum_lo += fast_exp2s(s01);
                if (c0 != r_hi)     sum_hi += fast_exp2s(s10);
                if (c0 + 1 != r_hi) sum_hi += fast_exp2s(s11);
            }
            #pragma unroll
            for (int o = 1; o < 4; o <<= 1) {
                sum_lo += __shfl_xor_sync(0xFFFFFFFFu, sum_lo, o);
                sum_hi += __shfl_xor_sync(0xFFFFFFFFu, sum_hi, o);
            }
            if ((lane & 3) == 0) {
                atomicAdd(&g_denom[r_lo], sum_lo);
                atomicAdd(&g_denom[r_hi], sum_hi);
            }
        }
    } else {
        // off-diagonal: every exp feeds a row sum AND a column sum (symmetry).
        float csum[8][2];
        #pragma unroll
        for (int nt = 0; nt < 8; nt++) { csum[nt][0] = 0.0f; csum[nt][1] = 0.0f; }

        #pragma unroll
        for (int mt = 0; mt < 2; mt++) {
            const int rl = warp_m * 32 + mt * 16 + g;
            const int r_lo = rowBase + rl;
            const int r_hi = r_lo + 8;
            const int p_lo = r_lo + BATCH;   // rows < cols here
            const int p_hi = r_hi + BATCH;
            const float sr_lo = sRow[rl];
            const float sr_hi = sRow[rl + 8];

            float sum_lo = 0.0f, sum_hi = 0.0f;
            #pragma unroll
            for (int nt = 0; nt < 8; nt++) {
                const int c0 = cb0 + nt * 8;
                const float sc0 = sCol[cl0 + nt * 8];
                const float sc1 = sCol[cl0 + nt * 8 + 1];
                const float s00 = (float)acc[mt][nt][0] * sr_lo * sc0;
                const float s01 = (float)acc[mt][nt][1] * sr_lo * sc1;
                const float s10 = (float)acc[mt][nt][2] * sr_hi * sc0;
                const float s11 = (float)acc[mt][nt][3] * sr_hi * sc1;
                const float e00 = fast_exp2s(s00);
                const float e01 = fast_exp2s(s01);
                const float e10 = fast_exp2s(s10);
                const float e11 = fast_exp2s(s11);
                sum_lo += e00 + e01;
                sum_hi += e10 + e11;
                csum[nt][0] += e00 + e10;
                csum[nt][1] += e01 + e11;
                if (c0 == p_lo)     { g_pos[r_lo] = s00; g_pos[c0] = s00; }
                if (c0 + 1 == p_lo) { g_pos[r_lo] = s01; g_pos[c0 + 1] = s01; }
                if (c0 == p_hi)     { g_pos[r_hi] = s10; g_pos[c0] = s10; }
                if (c0 + 1 == p_hi) { g_pos[r_hi] = s11; g_pos[c0 + 1] = s11; }
            }
            #pragma unroll
            for (int o = 1; o < 4; o <<= 1) {
                sum_lo += __shfl_xor_sync(0xFFFFFFFFu, sum_lo, o);
                sum_hi += __shfl_xor_sync(0xFFFFFFFFu, sum_hi, o);
            }
            if ((lane & 3) == 0) {
                atomicAdd(&g_denom[r_lo], sum_lo);
                atomicAdd(&g_denom[r_hi], sum_hi);
            }
        }

        #pragma unroll
        for (int nt = 0; nt < 8; nt++) {
            float c0s = csum[nt][0];
            float c1s = csum[nt][1];
            #pragma unroll
            for (int o = 4; o < 32; o <<= 1) {
                c0s += __shfl_xor_sync(0xFFFFFFFFu, c0s, o);
                c1s += __shfl_xor_sync(0xFFFFFFFFu, c1s, o);
            }
            if (g == 0) {
                const int c0 = cb0 + nt * 8;
                atomicAdd(&g_denom[c0], c0s);
                atomicAdd(&g_denom[c0 + 1], c1s);
            }
        }
    }
}

// ---------------------------------------------------------------------------
// Kernel 3: loss_r = log(denom_r) - 2*pos_r; mean -> scalar
// ---------------------------------------------------------------------------
__global__ __launch_bounds__(1024) void reduce_kernel(float* __restrict__ out) {
    __shared__ float s[1024];
    float v = 0.0f;
    for (int i = threadIdx.x; i < NTOT; i += 1024)
        v += logf(g_denom[i]) - 2.0f * g_pos[i];
    s[threadIdx.x] = v;
    __syncthreads();
    for (int stride = 512; stride > 0; stride >>= 1) {
        if (threadIdx.x < stride) s[threadIdx.x] += s[threadIdx.x + stride];
        __syncthreads();
    }
    if (threadIdx.x == 0) out[0] = s[0] * (1.0f / (float)NTOT);
}

// ---------------------------------------------------------------------------
extern "C" void kernel_launch(void* const* d_in, const int* in_sizes, int n_in,
                              void* d_out, int out_size) {
    const float* x_i = (const float*)d_in[0];
    const float* x_j = (const float*)d_in[1];
    float* out = (float*)d_out;

    cudaFuncSetAttribute(sim_kernel, cudaFuncAttributeMaxDynamicSharedMemorySize, SM_TOTAL);

    norm_kernel<<<NTOT / 8, 256>>>(x_i, x_j);
    sim_kernel<<<NCTAS, 256, SM_TOTAL>>>();
    reduce_kernel<<<1, 1024>>>(out);
}

// round 11
// speedup vs baseline: 2.3514x; 2.3514x over previous
#include <cuda_runtime.h>
#include <cuda_bf16.h>
#include <math.h>
#include <stdint.h>

// Problem constants
#define BATCH 4096
#define DIM   512
#define NTOT  8192
#define TILE  128
#define KCHUNK 64
#define NCHUNKS (DIM / KCHUNK)   // 8
#define NTILES  (NTOT / TILE)    // 64
#define NCTAS   (NTILES * (NTILES + 1) / 2)  // 2080 upper-tri tiles

// SMEM: double-buffered A and B tiles, each 128 rows x 64 bf16 = 16 KB
#define TILE_BYTES 16384
#define SM_A(buf) ((buf) * TILE_BYTES)
#define SM_B(buf) (2 * TILE_BYTES + (buf) * TILE_BYTES)
#define SM_TOTAL  (4 * TILE_BYTES)   // 64 KB -> 2 CTAs/SM

// Scratch (no cudaMalloc allowed)
__device__ __nv_bfloat16 g_zb[NTOT * DIM];   // normalized Z, bf16 (8 MB)
__device__ float g_denom[NTOT];
__device__ float g_pos[NTOT];

// ---------------------------------------------------------------------------
__device__ __forceinline__ uint32_t smem_u32(const void* p) {
    uint32_t a;
    asm("{ .reg .u64 t; cvta.to.shared.u64 t, %1; cvt.u32.u64 %0, t; }" : "=r"(a) : "l"(p));
    return a;
}

__device__ __forceinline__ void cp_async16(uint32_t saddr, const void* gptr) {
    asm volatile("cp.async.cg.shared.global [%0], [%1], 16;" :: "r"(saddr), "l"(gptr));
}
__device__ __forceinline__ void cp_commit() {
    asm volatile("cp.async.commit_group;" ::: "memory");
}
template <int N>
__device__ __forceinline__ void cp_wait() {
    asm volatile("cp.async.wait_group %0;" :: "n"(N) : "memory");
}

__device__ __forceinline__ void ldsm_x4(uint32_t* r, uint32_t addr) {
    asm volatile("ldmatrix.sync.aligned.m8n8.x4.shared.b16 {%0,%1,%2,%3}, [%4];"
                 : "=r"(r[0]), "=r"(r[1]), "=r"(r[2]), "=r"(r[3]) : "r"(addr));
}

__device__ __forceinline__ void mma16816(float* c, const uint32_t* a, const uint32_t* b) {
    asm volatile(
        "mma.sync.aligned.m16n8k16.row.col.f32.bf16.bf16.f32 "
        "{%0,%1,%2,%3}, {%4,%5,%6,%7}, {%8,%9}, {%0,%1,%2,%3};"
        : "+f"(c[0]), "+f"(c[1]), "+f"(c[2]), "+f"(c[3])
        : "r"(a[0]), "r"(a[1]), "r"(a[2]), "r"(a[3]), "r"(b[0]), "r"(b[1]));
}

// Fast exp(2*s) on the FMA pipe (avoid MUFU.EX2 throughput wall).
__device__ __forceinline__ float fast_exp2s(float s) {
    float t = 2.8853900817779268f * s;      // 2 * log2(e)
    float fn = rintf(t);
    float f = t - fn;
    float p = fmaf(0.0013333558f, f, 0.0096181291f);
    p = fmaf(p, f, 0.0555041087f);
    p = fmaf(p, f, 0.2402265070f);
    p = fmaf(p, f, 0.6931471806f);
    p = fmaf(p, f, 1.0f);
    int n = (int)fn;
    float scale = __int_as_float((n + 127) << 23);
    return p * scale;
}

// ---------------------------------------------------------------------------
// Kernel 1: L2-normalize rows into bf16 Z, one WARP per row (no block sync).
// Also zeroes accumulators. (Proven R9 version.)
// ---------------------------------------------------------------------------
__global__ __launch_bounds__(256) void norm_kernel(const float* __restrict__ xi,
                                                   const float* __restrict__ xj) {
    const int row = (blockIdx.x * 256 + threadIdx.x) >> 5;
    const int lane = threadIdx.x & 31;
    const float* src = (row < BATCH) ? (xi + (size_t)row * DIM)
                                     : (xj + (size_t)(row - BATCH) * DIM);
    float4 v[4];
    #pragma unroll
    for (int i = 0; i < 4; i++) v[i] = ((const float4*)src)[lane + 32 * i];

    float ss = 0.0f;
    #pragma unroll
    for (int i = 0; i < 4; i++)
        ss += v[i].x * v[i].x + v[i].y * v[i].y + v[i].z * v[i].z + v[i].w * v[i].w;
    #pragma unroll
    for (int o = 16; o > 0; o >>= 1) ss += __shfl_xor_sync(0xFFFFFFFFu, ss, o);

    const float inv = 1.0f / fmaxf(sqrtf(ss), 1e-12f);

    #pragma unroll
    for (int i = 0; i < 4; i++) {
        __nv_bfloat162 h0 = __floats2bfloat162_rn(v[i].x * inv, v[i].y * inv);
        __nv_bfloat162 h1 = __floats2bfloat162_rn(v[i].z * inv, v[i].w * inv);
        uint2 u;
        u.x = *(uint32_t*)&h0;
        u.y = *(uint32_t*)&h1;
        ((uint2*)(g_zb + (size_t)row * DIM))[lane + 32 * i] = u;
    }

    if (lane == 0) {
        g_denom[row] = 0.0f;
        g_pos[row] = 0.0f;
    }
}

// ---------------------------------------------------------------------------
// Kernel 2: symmetric-aware fused sim tiles (upper-tri only).
// 128 threads = 4 warps in a 2x2 grid, each warp computes a 64x64 sub-tile
// (128 B of smem fragments per MMA vs 192 B for 32x64 -> smem no longer
// co-bound with tensor). Same proven 2-stage cp.async schedule as R5/R9.
// ---------------------------------------------------------------------------
__global__ void __launch_bounds__(128, 2) sim_kernel() {
    extern __shared__ char smem[];
    const uint32_t sbase = smem_u32(smem);
    const int tid = threadIdx.x;
    const int wid = tid >> 5;
    const int lane = tid & 31;

    // triangular decode: off(i) = i*64 - i*(i-1)/2
    const int t = blockIdx.x;
    int by = (int)(64.5f - sqrtf(64.5f * 64.5f - 2.0f * (float)t));
    while ((by + 1) * NTILES - ((by + 1) * by) / 2 <= t) by++;
    while (by * NTILES - (by * (by - 1)) / 2 > t) by--;
    const int bx = by + (t - (by * NTILES - (by * (by - 1)) / 2));

    const int rowBase = by * TILE;
    const int colBase = bx * TILE;
    const bool diag = (by == bx);

    const int warp_m = wid & 1;     // 0..1 -> 64-row strip
    const int warp_n = wid >> 1;    // 0..1 -> 64-col strip

    const __nv_bfloat16* __restrict__ zb = g_zb;

    // --- cp.async load mapping: 1024 16B units per tile, 8 per thread.
    // With 128 threads, (idx & 7) and (r & 7) are it-invariant:
    // idx = tid + it*128 -> r = (tid>>3) + 16*it, c16 = tid&7.
    const int r0 = tid >> 3;           // 0..15
    const int c16 = tid & 7;
    const uint32_t soff0 = (uint32_t)(r0 * 128 + ((c16 * 16) ^ ((r0 & 7) << 4)));
    const __nv_bfloat16* ga0 = zb + (size_t)(rowBase + r0) * DIM + c16 * 8;
    const __nv_bfloat16* gb0 = zb + (size_t)(colBase + r0) * DIM + c16 * 8;

    // --- ldmatrix address components (swizzle folded into col xor) ---
    uint32_t aRow[4], aMask[4];
    #pragma unroll
    for (int mt = 0; mt < 4; mt++) {
        int r = warp_m * 64 + mt * 16 + (lane & 15);
        aRow[mt] = (uint32_t)(r * 128);
        aMask[mt] = (uint32_t)((r & 7) << 4);
    }
    const uint32_t aColK = (uint32_t)((lane >> 4) * 16);

    uint32_t bRow[4], bMask[4];
    const int q = lane >> 3;
    #pragma unroll
    for (int p = 0; p < 4; p++) {
        int r = warp_n * 64 + (2 * p + (q >> 1)) * 8 + (lane & 7);
        bRow[p] = (uint32_t)(r * 128);
        bMask[p] = (uint32_t)((r & 7) << 4);
    }
    const uint32_t bColK = (uint32_t)((q & 1) * 16);

    float acc[4][8][4];
    #pragma unroll
    for (int mt = 0; mt < 4; mt++)
        #pragma unroll
        for (int nt = 0; nt < 8; nt++)
            #pragma unroll
            for (int k = 0; k < 4; k++) acc[mt][nt][k] = 0.0f;

    // --- prologue: chunk 0 -> buffer 0 ---
    #pragma unroll
    for (int it = 0; it < 8; it++) {
        cp_async16(sbase + SM_A(0) + soff0 + 2048u * it, ga0 + (size_t)16 * it * DIM);
        cp_async16(sbase + SM_B(0) + soff0 + 2048u * it, gb0 + (size_t)16 * it * DIM);
    }
    cp_commit();

    for (int kk = 0; kk < NCHUNKS; kk++) {
        const int buf = kk & 1;
        if (kk + 1 < NCHUNKS) {
            const int nb = (kk + 1) & 1;
            const int koff = (kk + 1) * KCHUNK;
            #pragma unroll
            for (int it = 0; it < 8; it++) {
                cp_async16(sbase + SM_A(nb) + soff0 + 2048u * it,
                           ga0 + (size_t)16 * it * DIM + koff);
                cp_async16(sbase + SM_B(nb) + soff0 + 2048u * it,
                           gb0 + (size_t)16 * it * DIM + koff);
            }
            cp_commit();
            cp_wait<1>();
        } else {
            cp_wait<0>();
        }
        __syncthreads();

        const uint32_t abase = sbase + SM_A(buf);
        const uint32_t bbase = sbase + SM_B(buf);

        #pragma unroll
        for (int kt = 0; kt < 4; kt++) {
            const uint32_t kb = (uint32_t)(kt * 32);
            uint32_t a[4][4];
            #pragma unroll
            for (int mt = 0; mt < 4; mt++)
                ldsm_x4(a[mt], abase + aRow[mt] + ((kb + aColK) ^ aMask[mt]));

            uint32_t b[8][2];
            #pragma unroll
            for (int p = 0; p < 4; p++) {
                uint32_t r4[4];
                ldsm_x4(r4, bbase + bRow[p] + ((kb + bColK) ^ bMask[p]));
                b[2 * p][0] = r4[0]; b[2 * p][1] = r4[1];
                b[2 * p + 1][0] = r4[2]; b[2 * p + 1][1] = r4[3];
            }

            #pragma unroll
            for (int mt = 0; mt < 4; mt++)
                #pragma unroll
                for (int nt = 0; nt < 8; nt++)
                    mma16816(acc[mt][nt], a[mt], b[nt]);
        }
        __syncthreads();   // protect buffers before next iteration's cp.async
    }

    // --- fused epilogue ---
    // fragment map: c0,c1 -> row g=lane>>2, cols cb0, cb0+1 ; c2,c3 -> row g+8
    const int g = lane >> 2;
    const int cb0 = colBase + warp_n * 64 + (lane & 3) * 2;

    if (diag) {
        #pragma unroll
        for (int mt = 0; mt < 4; mt++) {
            const int r_lo = rowBase + warp_m * 64 + mt * 16 + g;
            const int r_hi = r_lo + 8;
            float sum_lo = 0.0f, sum_hi = 0.0f;
            #pragma unroll
            for (int nt = 0; nt < 8; nt++) {
                const int c0 = cb0 + nt * 8;
                if (c0 != r_lo)     sum_lo += fast_exp2s(acc[mt][nt][0]);
                if (c0 + 1 != r_lo) sum_lo += fast_exp2s(acc[mt][nt][1]);
                if (c0 != r_hi)     sum_hi += fast_exp2s(acc[mt][nt][2]);
                if (c0 + 1 != r_hi) sum_hi += fast_exp2s(acc[mt][nt][3]);
            }
            #pragma unroll
            for (int o = 1; o < 4; o <<= 1) {
                sum_lo += __shfl_xor_sync(0xFFFFFFFFu, sum_lo, o);
                sum_hi += __shfl_xor_sync(0xFFFFFFFFu, sum_hi, o);
            }
            if ((lane & 3) == 0) {
                atomicAdd(&g_denom[r_lo], sum_lo);
                atomicAdd(&g_denom[r_hi], sum_hi);
            }
        }
    } else {
        // off-diagonal: every exp feeds a row sum AND a column sum (symmetry).
        float csum[8][2];
        #pragma unroll
        for (int nt = 0; nt < 8; nt++) { csum[nt][0] = 0.0f; csum[nt][1] = 0.0f; }

        #pragma unroll
        for (int mt = 0; mt < 4; mt++) {
            const int r_lo = rowBase + warp_m * 64 + mt * 16 + g;
            const int r_hi = r_lo + 8;
            const int p_lo = r_lo + BATCH;   // rows < cols here
            const int p_hi = r_hi + BATCH;

            float sum_lo = 0.0f, sum_hi = 0.0f;
            #pragma unroll
            for (int nt = 0; nt < 8; nt++) {
                const int c0 = cb0 + nt * 8;
                const float s00 = acc[mt][nt][0];
                const float s01 = acc[mt][nt][1];
                const float s10 = acc[mt][nt][2];
                const float s11 = acc[mt][nt][3];
                const float e00 = fast_exp2s(s00);
                const float e01 = fast_exp2s(s01);
                const float e10 = fast_exp2s(s10);
                const float e11 = fast_exp2s(s11);
                sum_lo += e00 + e01;
                sum_hi += e10 + e11;
                csum[nt][0] += e00 + e10;
                csum[nt][1] += e01 + e11;
                if (c0 == p_lo)     { g_pos[r_lo] = s00; g_pos[c0] = s00; }
                if (c0 + 1 == p_lo) { g_pos[r_lo] = s01; g_pos[c0 + 1] = s01; }
                if (c0 == p_hi)     { g_pos[r_hi] = s10; g_pos[c0] = s10; }
                if (c0 + 1 == p_hi) { g_pos[r_hi] = s11; g_pos[c0 + 1] = s11; }
            }
            #pragma unroll
            for (int o = 1; o < 4; o <<= 1) {
                sum_lo += __shfl_xor_sync(0xFFFFFFFFu, sum_lo, o);
                sum_hi += __shfl_xor_sync(0xFFFFFFFFu, sum_hi, o);
            }
            if ((lane & 3) == 0) {
                atomicAdd(&g_denom[r_lo], sum_lo);
                atomicAdd(&g_denom[r_hi], sum_hi);
            }
        }

        #pragma unroll
        for (int nt = 0; nt < 8; nt++) {
            float c0s = csum[nt][0];
            float c1s = csum[nt][1];
            #pragma unroll
            for (int o = 4; o < 32; o <<= 1) {
                c0s += __shfl_xor_sync(0xFFFFFFFFu, c0s, o);
                c1s += __shfl_xor_sync(0xFFFFFFFFu, c1s, o);
            }
            if (g == 0) {
                const int c0 = cb0 + nt * 8;
                atomicAdd(&g_denom[c0], c0s);
                atomicAdd(&g_denom[c0 + 1], c1s);
            }
        }
    }
}

// ---------------------------------------------------------------------------
// Kernel 3: loss_r = log(denom_r) - 2*pos_r; mean -> scalar
// ---------------------------------------------------------------------------
__global__ __launch_bounds__(1024) void reduce_kernel(float* __restrict__ out) {
    __shared__ float s[1024];
    float v = 0.0f;
    for (int i = threadIdx.x; i < NTOT; i += 1024)
        v += logf(g_denom[i]) - 2.0f * g_pos[i];
    s[threadIdx.x] = v;
    __syncthreads();
    for (int stride = 512; stride > 0; stride >>= 1) {
        if (threadIdx.x < stride) s[threadIdx.x] += s[threadIdx.x + stride];
        __syncthreads();
    }
    if (threadIdx.x == 0) out[0] = s[0] * (1.0f / (float)NTOT);
}

// ---------------------------------------------------------------------------
extern "C" void kernel_launch(void* const* d_in, const int* in_sizes, int n_in,
                              void* d_out, int out_size) {
    const float* x_i = (const float*)d_in[0];
    const float* x_j = (const float*)d_in[1];
    float* out = (float*)d_out;

    cudaFuncSetAttribute(sim_kernel, cudaFuncAttributeMaxDynamicSharedMemorySize, SM_TOTAL);

    norm_kernel<<<NTOT / 8, 256>>>(x_i, x_j);
    sim_kernel<<<NCTAS, 128, SM_TOTAL>>>();
    reduce_kernel<<<1, 1024>>>(out);
}

// round 12
// speedup vs baseline: 2.4509x; 1.0423x over previous
#include <cuda_runtime.h>
#include <cuda_bf16.h>
#include <math.h>
#include <stdint.h>

// Problem constants
#define BATCH 4096
#define DIM   512
#define NTOT  8192
#define TILE  128
#define KCHUNK 64
#define NCHUNKS (DIM / KCHUNK)   // 8
#define NTILES  (NTOT / TILE)    // 64
#define NCTAS   (NTILES * (NTILES + 1) / 2)  // 2080 upper-tri tiles

// SMEM: double-buffered A and B tiles, each 128 rows x 64 bf16 = 16 KB
#define TILE_BYTES 16384
#define SM_A(buf) ((buf) * TILE_BYTES)
#define SM_B(buf) (2 * TILE_BYTES + (buf) * TILE_BYTES)
#define SM_TOTAL  (4 * TILE_BYTES)   // 64 KB -> 2 CTAs/SM

// Scratch (no cudaMalloc allowed)
__device__ __nv_bfloat16 g_zb[NTOT * DIM];   // normalized Z, bf16 (8 MB)
__device__ float g_denom[NTOT];
__device__ float g_pos[NTOT];

// ---------------------------------------------------------------------------
__device__ __forceinline__ uint32_t smem_u32(const void* p) {
    uint32_t a;
    asm("{ .reg .u64 t; cvta.to.shared.u64 t, %1; cvt.u32.u64 %0, t; }" : "=r"(a) : "l"(p));
    return a;
}

__device__ __forceinline__ void cp_async16(uint32_t saddr, const void* gptr) {
    asm volatile("cp.async.cg.shared.global [%0], [%1], 16;" :: "r"(saddr), "l"(gptr));
}
__device__ __forceinline__ void cp_commit() {
    asm volatile("cp.async.commit_group;" ::: "memory");
}
template <int N>
__device__ __forceinline__ void cp_wait() {
    asm volatile("cp.async.wait_group %0;" :: "n"(N) : "memory");
}

__device__ __forceinline__ void ldsm_x4(uint32_t* r, uint32_t addr) {
    asm volatile("ldmatrix.sync.aligned.m8n8.x4.shared.b16 {%0,%1,%2,%3}, [%4];"
                 : "=r"(r[0]), "=r"(r[1]), "=r"(r[2]), "=r"(r[3]) : "r"(addr));
}

__device__ __forceinline__ void mma16816(float* c, const uint32_t* a, const uint32_t* b) {
    asm volatile(
        "mma.sync.aligned.m16n8k16.row.col.f32.bf16.bf16.f32 "
        "{%0,%1,%2,%3}, {%4,%5,%6,%7}, {%8,%9}, {%0,%1,%2,%3};"
        : "+f"(c[0]), "+f"(c[1]), "+f"(c[2]), "+f"(c[3])
        : "r"(a[0]), "r"(a[1]), "r"(a[2]), "r"(a[3]), "r"(b[0]), "r"(b[1]));
}

// Fast exp(2*s) on the FMA pipe (avoid MUFU.EX2 throughput wall).
__device__ __forceinline__ float fast_exp2s(float s) {
    float t = 2.8853900817779268f * s;      // 2 * log2(e)
    float fn = rintf(t);
    float f = t - fn;
    float p = fmaf(0.0013333558f, f, 0.0096181291f);
    p = fmaf(p, f, 0.0555041087f);
    p = fmaf(p, f, 0.2402265070f);
    p = fmaf(p, f, 0.6931471806f);
    p = fmaf(p, f, 1.0f);
    int n = (int)fn;
    float scale = __int_as_float((n + 127) << 23);
    return p * scale;
}

// ---------------------------------------------------------------------------
// Kernel 1: L2-normalize rows into bf16 Z. One warp handles TWO rows with all
// 8 float4 loads front-batched (MLP=8) to push DRAM harder. Zeroes
// accumulators and the output scalar.
// ---------------------------------------------------------------------------
__global__ __launch_bounds__(256) void norm_kernel(const float* __restrict__ xi,
                                                   const float* __restrict__ xj,
                                                   float* __restrict__ out) {
    const int warp = (blockIdx.x * 256 + threadIdx.x) >> 5;   // 0..4095
    const int lane = threadIdx.x & 31;
    const int row0 = warp * 2;
    const int row1 = row0 + 1;

    const float* src0 = (row0 < BATCH) ? (xi + (size_t)row0 * DIM)
                                       : (xj + (size_t)(row0 - BATCH) * DIM);
    const float* src1 = (row1 < BATCH) ? (xi + (size_t)row1 * DIM)
                                       : (xj + (size_t)(row1 - BATCH) * DIM);

    float4 v0[4], v1[4];
    #pragma unroll
    for (int i = 0; i < 4; i++) v0[i] = ((const float4*)src0)[lane + 32 * i];
    #pragma unroll
    for (int i = 0; i < 4; i++) v1[i] = ((const float4*)src1)[lane + 32 * i];

    float ss0 = 0.0f, ss1 = 0.0f;
    #pragma unroll
    for (int i = 0; i < 4; i++) {
        ss0 += v0[i].x * v0[i].x + v0[i].y * v0[i].y + v0[i].z * v0[i].z + v0[i].w * v0[i].w;
        ss1 += v1[i].x * v1[i].x + v1[i].y * v1[i].y + v1[i].z * v1[i].z + v1[i].w * v1[i].w;
    }
    #pragma unroll
    for (int o = 16; o > 0; o >>= 1) {
        ss0 += __shfl_xor_sync(0xFFFFFFFFu, ss0, o);
        ss1 += __shfl_xor_sync(0xFFFFFFFFu, ss1, o);
    }

    const float inv0 = 1.0f / fmaxf(sqrtf(ss0), 1e-12f);
    const float inv1 = 1.0f / fmaxf(sqrtf(ss1), 1e-12f);

    #pragma unroll
    for (int i = 0; i < 4; i++) {
        __nv_bfloat162 h0 = __floats2bfloat162_rn(v0[i].x * inv0, v0[i].y * inv0);
        __nv_bfloat162 h1 = __floats2bfloat162_rn(v0[i].z * inv0, v0[i].w * inv0);
        uint2 u;
        u.x = *(uint32_t*)&h0;
        u.y = *(uint32_t*)&h1;
        ((uint2*)(g_zb + (size_t)row0 * DIM))[lane + 32 * i] = u;
    }
    #pragma unroll
    for (int i = 0; i < 4; i++) {
        __nv_bfloat162 h0 = __floats2bfloat162_rn(v1[i].x * inv1, v1[i].y * inv1);
        __nv_bfloat162 h1 = __floats2bfloat162_rn(v1[i].z * inv1, v1[i].w * inv1);
        uint2 u;
        u.x = *(uint32_t*)&h0;
        u.y = *(uint32_t*)&h1;
        ((uint2*)(g_zb + (size_t)row1 * DIM))[lane + 32 * i] = u;
    }

    if (lane == 0) {
        g_denom[row0] = 0.0f;
        g_denom[row1] = 0.0f;
        g_pos[row0] = 0.0f;
        g_pos[row1] = 0.0f;
    }
    if (blockIdx.x == 0 && threadIdx.x == 0) out[0] = 0.0f;
}

// ---------------------------------------------------------------------------
// Kernel 2: symmetric-aware fused sim tiles (upper-tri only) — EXACT R9 body
// (best measured: 106.3 us total). 2-stage cp.async mainloop, register-fused
// exp/rowsum/colsum epilogue. DO NOT TOUCH (compilation-context sensitive).
// ---------------------------------------------------------------------------
__global__ __launch_bounds__(256, 2) void sim_kernel() {
    extern __shared__ char smem[];
    const uint32_t sbase = smem_u32(smem);
    const int tid = threadIdx.x;
    const int wid = tid >> 5;
    const int lane = tid & 31;

    // triangular decode: off(i) = i*64 - i*(i-1)/2
    const int t = blockIdx.x;
    int by = (int)(64.5f - sqrtf(64.5f * 64.5f - 2.0f * (float)t));
    while ((by + 1) * NTILES - ((by + 1) * by) / 2 <= t) by++;
    while (by * NTILES - (by * (by - 1)) / 2 > t) by--;
    const int bx = by + (t - (by * NTILES - (by * (by - 1)) / 2));

    const int rowBase = by * TILE;
    const int colBase = bx * TILE;
    const bool diag = (by == bx);

    const int warp_m = wid & 3;     // 0..3 -> 32-row strip
    const int warp_n = wid >> 2;    // 0..1 -> 64-col strip

    const __nv_bfloat16* __restrict__ zb = g_zb;

    // --- cp.async load mapping: 1024 16B units per tile, 4 per thread ---
    uint32_t ld_soff[4];
    const __nv_bfloat16* ld_ga[4];
    const __nv_bfloat16* ld_gb[4];
    #pragma unroll
    for (int it = 0; it < 4; it++) {
        int idx = tid + it * 256;
        int r = idx >> 3;
        int c16 = idx & 7;
        ld_soff[it] = (uint32_t)(r * 128 + ((c16 * 16) ^ ((r & 7) << 4)));
        ld_ga[it] = zb + (size_t)(rowBase + r) * DIM + c16 * 8;
        ld_gb[it] = zb + (size_t)(colBase + r) * DIM + c16 * 8;
    }

    // --- ldmatrix address components (swizzle folded into col xor) ---
    uint32_t aRow[2], aMask[2];
    #pragma unroll
    for (int mt = 0; mt < 2; mt++) {
        int r = warp_m * 32 + mt * 16 + (lane & 15);
        aRow[mt] = (uint32_t)(r * 128);
        aMask[mt] = (uint32_t)((r & 7) << 4);
    }
    const uint32_t aColK = (uint32_t)((lane >> 4) * 16);

    uint32_t bRow[4], bMask[4];
    const int q = lane >> 3;
    #pragma unroll
    for (int p = 0; p < 4; p++) {
        int r = warp_n * 64 + (2 * p + (q >> 1)) * 8 + (lane & 7);
        bRow[p] = (uint32_t)(r * 128);
        bMask[p] = (uint32_t)((r & 7) << 4);
    }
    const uint32_t bColK = (uint32_t)((q & 1) * 16);

    float acc[2][8][4];
    #pragma unroll
    for (int mt = 0; mt < 2; mt++)
        #pragma unroll
        for (int nt = 0; nt < 8; nt++)
            #pragma unroll
            for (int k = 0; k < 4; k++) acc[mt][nt][k] = 0.0f;

    // --- prologue: chunk 0 -> buffer 0 ---
    #pragma unroll
    for (int it = 0; it < 4; it++) {
        cp_async16(sbase + SM_A(0) + ld_soff[it], ld_ga[it]);
        cp_async16(sbase + SM_B(0) + ld_soff[it], ld_gb[it]);
    }
    cp_commit();

    for (int kk = 0; kk < NCHUNKS; kk++) {
        const int buf = kk & 1;
        if (kk + 1 < NCHUNKS) {
            const int nb = (kk + 1) & 1;
            const int koff = (kk + 1) * KCHUNK;
            #pragma unroll
            for (int it = 0; it < 4; it++) {
                cp_async16(sbase + SM_A(nb) + ld_soff[it], ld_ga[it] + koff);
                cp_async16(sbase + SM_B(nb) + ld_soff[it], ld_gb[it] + koff);
            }
            cp_commit();
            cp_wait<1>();
        } else {
            cp_wait<0>();
        }
        __syncthreads();

        const uint32_t abase = sbase + SM_A(buf);
        const uint32_t bbase = sbase + SM_B(buf);

        #pragma unroll
        for (int kt = 0; kt < 4; kt++) {
            const uint32_t kb = (uint32_t)(kt * 32);
            uint32_t a[2][4];
            #pragma unroll
            for (int mt = 0; mt < 2; mt++)
                ldsm_x4(a[mt], abase + aRow[mt] + ((kb + aColK) ^ aMask[mt]));

            uint32_t b[8][2];
            #pragma unroll
            for (int p = 0; p < 4; p++) {
                uint32_t r4[4];
                ldsm_x4(r4, bbase + bRow[p] + ((kb + bColK) ^ bMask[p]));
                b[2 * p][0] = r4[0]; b[2 * p][1] = r4[1];
                b[2 * p + 1][0] = r4[2]; b[2 * p + 1][1] = r4[3];
            }

            #pragma unroll
            for (int mt = 0; mt < 2; mt++)
                #pragma unroll
                for (int nt = 0; nt < 8; nt++)
                    mma16816(acc[mt][nt], a[mt], b[nt]);
        }
        __syncthreads();   // protect buffers before next iteration's cp.async
    }

    // --- fused epilogue ---
    // fragment map: c0,c1 -> row g=lane>>2, cols cb0, cb0+1 ; c2,c3 -> row g+8
    const int g = lane >> 2;
    const int cb0 = colBase + warp_n * 64 + (lane & 3) * 2;

    if (diag) {
        #pragma unroll
        for (int mt = 0; mt < 2; mt++) {
            const int r_lo = rowBase + warp_m * 32 + mt * 16 + g;
            const int r_hi = r_lo + 8;
            float sum_lo = 0.0f, sum_hi = 0.0f;
            #pragma unroll
            for (int nt = 0; nt < 8; nt++) {
                const int c0 = cb0 + nt * 8;
                if (c0 != r_lo)     sum_lo += fast_exp2s(acc[mt][nt][0]);
                if (c0 + 1 != r_lo) sum_lo += fast_exp2s(acc[mt][nt][1]);
                if (c0 != r_hi)     sum_hi += fast_exp2s(acc[mt][nt][2]);
                if (c0 + 1 != r_hi) sum_hi += fast_exp2s(acc[mt][nt][3]);
            }
            #pragma unroll
            for (int o = 1; o < 4; o <<= 1) {
                sum_lo += __shfl_xor_sync(0xFFFFFFFFu, sum_lo, o);
                sum_hi += __shfl_xor_sync(0xFFFFFFFFu, sum_hi, o);
            }
            if ((lane & 3) == 0) {
                atomicAdd(&g_denom[r_lo], sum_lo);
                atomicAdd(&g_denom[r_hi], sum_hi);
            }
        }
    } else {
        // off-diagonal: every exp feeds a row sum AND a column sum (symmetry).
        float csum[8][2];
        #pragma unroll
        for (int nt = 0; nt < 8; nt++) { csum[nt][0] = 0.0f; csum[nt][1] = 0.0f; }

        #pragma unroll
        for (int mt = 0; mt < 2; mt++) {
            const int r_lo = rowBase + warp_m * 32 + mt * 16 + g;
            const int r_hi = r_lo + 8;
            const int p_lo = r_lo + BATCH;   // rows < cols here
            const int p_hi = r_hi + BATCH;

            float sum_lo = 0.0f, sum_hi = 0.0f;
            #pragma unroll
            for (int nt = 0; nt < 8; nt++) {
                const int c0 = cb0 + nt * 8;
                const float s00 = acc[mt][nt][0];
                const float s01 = acc[mt][nt][1];
                const float s10 = acc[mt][nt][2];
                const float s11 = acc[mt][nt][3];
                const float e00 = fast_exp2s(s00);
                const float e01 = fast_exp2s(s01);
                const float e10 = fast_exp2s(s10);
                const float e11 = fast_exp2s(s11);
                sum_lo += e00 + e01;
                sum_hi += e10 + e11;
                csum[nt][0] += e00 + e10;
                csum[nt][1] += e01 + e11;
                if (c0 == p_lo)     { g_pos[r_lo] = s00; g_pos[c0] = s00; }
                if (c0 + 1 == p_lo) { g_pos[r_lo] = s01; g_pos[c0 + 1] = s01; }
                if (c0 == p_hi)     { g_pos[r_hi] = s10; g_pos[c0] = s10; }
                if (c0 + 1 == p_hi) { g_pos[r_hi] = s11; g_pos[c0 + 1] = s11; }
            }
            #pragma unroll
            for (int o = 1; o < 4; o <<= 1) {
                sum_lo += __shfl_xor_sync(0xFFFFFFFFu, sum_lo, o);
                sum_hi += __shfl_xor_sync(0xFFFFFFFFu, sum_hi, o);
            }
            if ((lane & 3) == 0) {
                atomicAdd(&g_denom[r_lo], sum_lo);
                atomicAdd(&g_denom[r_hi], sum_hi);
            }
        }

        #pragma unroll
        for (int nt = 0; nt < 8; nt++) {
            float c0s = csum[nt][0];
            float c1s = csum[nt][1];
            #pragma unroll
            for (int o = 4; o < 32; o <<= 1) {
                c0s += __shfl_xor_sync(0xFFFFFFFFu, c0s, o);
                c1s += __shfl_xor_sync(0xFFFFFFFFu, c1s, o);
            }
            if (g == 0) {
                const int c0 = cb0 + nt * 8;
                atomicAdd(&g_denom[c0], c0s);
                atomicAdd(&g_denom[c0 + 1], c1s);
            }
        }
    }
}

// ---------------------------------------------------------------------------
// Kernel 3: distributed final reduction. 8 blocks x 1024 threads; each block
// covers 1024 rows, block-reduces, then one atomicAdd into out (zeroed by
// norm_kernel earlier in the same launch sequence).
// ---------------------------------------------------------------------------
__global__ __launch_bounds__(1024) void reduce_kernel(float* __restrict__ out) {
    __shared__ float s[1024];
    const int i = blockIdx.x * 1024 + threadIdx.x;
    s[threadIdx.x] = logf(g_denom[i]) - 2.0f * g_pos[i];
    __syncthreads();
    for (int stride = 512; stride > 0; stride >>= 1) {
        if (threadIdx.x < stride) s[threadIdx.x] += s[threadIdx.x + stride];
        __syncthreads();
    }
    if (threadIdx.x == 0) atomicAdd(out, s[0] * (1.0f / (float)NTOT));
}

// ---------------------------------------------------------------------------
extern "C" void kernel_launch(void* const* d_in, const int* in_sizes, int n_in,
                              void* d_out, int out_size) {
    const float* x_i = (const float*)d_in[0];
    const float* x_j = (const float*)d_in[1];
    float* out = (float*)d_out;

    cudaFuncSetAttribute(sim_kernel, cudaFuncAttributeMaxDynamicSharedMemorySize, SM_TOTAL);

    norm_kernel<<<NTOT / 16, 256>>>(x_i, x_j, out);   // 512 blocks, 2 rows/warp
    sim_kernel<<<NCTAS, 256, SM_TOTAL>>>();
    reduce_kernel<<<NTOT / 1024, 1024>>>(out);        // 8 blocks
}